// round 11
// baseline (speedup 1.0000x reference)
#include <cuda_runtime.h>

// IDWT (inverse Haar) — streaming kernel with 256-bit stores (sm_100+ st.global.v8.f32).
// Inputs: LL, LH, HL, HH each [B=16, C=64, H2=128, W2=128] fp32.
// Output: [16, 64, 256, 256] fp32.
// out[2i,2j]=a, out[2i,2j+1]=b, out[2i+1,2j]=c, out[2i+1,2j+1]=d where
//   a=(LL+LH+HL+HH)/2, b=(LL+LH-HL-HH)/2, c=(LL-LH+HL-HH)/2, d=(LL-LH-HL+HH)/2
//
// One thread per float4 of input (4 coefficients). Per output row a thread
// produces 8 contiguous floats (32B) at float4 slots {2l, 2l+1}; with a single
// st.global.v8.f32 this is one dense instruction — consecutive lanes write
// consecutive 32B chunks, so each STG covers a fully-dense 1024B wavefront
// (a whole output row per warp). Loads: 4 independent LDG.128 per thread.
// All traffic is touch-once -> .cs streaming policy everywhere.

static constexpr int W2 = 128;                   // input width
static constexpr int H2 = 128;                   // input height
static constexpr int W4 = W2 / 4;                // float4 groups per input row = 32
static constexpr int OUT_ROW_F4 = (2 * W2) / 4;  // 64 float4 per output row

static constexpr int BLOCK = 256;

__device__ __forceinline__ void stcs_v8(float4* p,
                                        float f0, float f1, float f2, float f3,
                                        float f4, float f5, float f6, float f7)
{
    asm volatile(
        "st.global.cs.v8.f32 [%0], {%1, %2, %3, %4, %5, %6, %7, %8};"
        :: "l"(p),
           "f"(f0), "f"(f1), "f"(f2), "f"(f3),
           "f"(f4), "f"(f5), "f"(f6), "f"(f7)
        : "memory");
}

__global__ void __launch_bounds__(BLOCK) idwt_haar_kernel(
    const float4* __restrict__ ll4,
    const float4* __restrict__ lh4,
    const float4* __restrict__ hl4,
    const float4* __restrict__ hh4,
    float4* __restrict__ out4)
{
    unsigned idx = blockIdx.x * BLOCK + threadIdx.x;   // one per 4 input coeffs

    float4 ll = __ldcs(&ll4[idx]);
    float4 lh = __ldcs(&lh4[idx]);
    float4 hl = __ldcs(&hl4[idx]);
    float4 hh = __ldcs(&hh4[idx]);

    float4 a, b, c, d;
    {
        float s0, s1, d0, d1;
        s0 = ll.x + lh.x; s1 = hl.x + hh.x; d0 = ll.x - lh.x; d1 = hl.x - hh.x;
        a.x = 0.5f * (s0 + s1); b.x = 0.5f * (s0 - s1);
        c.x = 0.5f * (d0 + d1); d.x = 0.5f * (d0 - d1);
        s0 = ll.y + lh.y; s1 = hl.y + hh.y; d0 = ll.y - lh.y; d1 = hl.y - hh.y;
        a.y = 0.5f * (s0 + s1); b.y = 0.5f * (s0 - s1);
        c.y = 0.5f * (d0 + d1); d.y = 0.5f * (d0 - d1);
        s0 = ll.z + lh.z; s1 = hl.z + hh.z; d0 = ll.z - lh.z; d1 = hl.z - hh.z;
        a.z = 0.5f * (s0 + s1); b.z = 0.5f * (s0 - s1);
        c.z = 0.5f * (d0 + d1); d.z = 0.5f * (d0 - d1);
        s0 = ll.w + lh.w; s1 = hl.w + hh.w; d0 = ll.w - lh.w; d1 = hl.w - hh.w;
        a.w = 0.5f * (s0 + s1); b.w = 0.5f * (s0 - s1);
        c.w = 0.5f * (d0 + d1); d.w = 0.5f * (d0 - d1);
    }

    // idx = plane*4096 + row*32 + col4 (col4 in [0,32), row in [0,128), plane in [0,1024)).
    unsigned col4  = idx & (W4 - 1);          // 0..31
    unsigned row   = (idx >> 5) & (H2 - 1);   // 0..127
    unsigned plane = idx >> 12;               // 0..1023

    // Output base (float4 units) — even, so 32B-aligned for v8 stores. Max < 2^25.
    unsigned base = plane * (2u * H2 * OUT_ROW_F4)
                  + (2u * row) * OUT_ROW_F4
                  + col4 * 2u;

    // Row 2i:   [a0,b0,a1,b1,a2,b2,a3,b3]  — one 256-bit store
    stcs_v8(&out4[base],
            a.x, b.x, a.y, b.y, a.z, b.z, a.w, b.w);
    // Row 2i+1: [c0,d0,c1,d1,c2,d2,c3,d3]  — one 256-bit store
    stcs_v8(&out4[base + OUT_ROW_F4],
            c.x, d.x, c.y, d.y, c.z, d.z, c.w, d.w);
}

extern "C" void kernel_launch(void* const* d_in, const int* in_sizes, int n_in,
                              void* d_out, int out_size)
{
    const float4* ll = (const float4*)d_in[0];
    const float4* lh = (const float4*)d_in[1];
    const float4* hl = (const float4*)d_in[2];
    const float4* hh = (const float4*)d_in[3];
    float4* out = (float4*)d_out;

    int n_groups = in_sizes[0] / 4;              // 2^22
    int grid = (n_groups + BLOCK - 1) / BLOCK;   // 16384
    idwt_haar_kernel<<<grid, BLOCK>>>(ll, lh, hl, hh, out);
}

// round 12
// speedup vs baseline: 1.0169x; 1.0169x over previous
#include <cuda_runtime.h>

// IDWT (inverse Haar) — streaming kernel, dense-store layout + streaming cache hints.
// R9 winner structure; only change: BLOCK 256 -> 512 (micro-tune).
// Inputs: LL, LH, HL, HH each [B=16, C=64, H2=128, W2=128] fp32.
// Output: [16, 64, 256, 256] fp32.
// out[2i,2j]=a, out[2i,2j+1]=b, out[2i+1,2j]=c, out[2i+1,2j+1]=d where
//   a=(LL+LH+HL+HH)/2, b=(LL+LH-HL-HH)/2, c=(LL-LH+HL-HH)/2, d=(LL-LH-HL+HH)/2
//
// One thread per float2 (2 coefficients). Each thread writes exactly one
// float4 into each of two output rows; consecutive lanes hit consecutive
// float4s -> every STG.128 is a dense 512B warp transaction. Touch-once
// traffic -> .cs streaming policy on all loads/stores.

static constexpr int W2 = 128;                   // input width
static constexpr int H2 = 128;                   // input height
static constexpr int W2F2 = W2 / 2;              // float2 groups per input row = 64
static constexpr int OUT_ROW_F4 = (2 * W2) / 4;  // 64 float4 per output row

static constexpr int BLOCK = 512;

__global__ void __launch_bounds__(BLOCK) idwt_haar_kernel(
    const float2* __restrict__ ll2,
    const float2* __restrict__ lh2,
    const float2* __restrict__ hl2,
    const float2* __restrict__ hh2,
    float4* __restrict__ out4)
{
    unsigned idx = blockIdx.x * BLOCK + threadIdx.x;   // one per 2 input coeffs

    float2 ll = __ldcs(&ll2[idx]);
    float2 lh = __ldcs(&lh2[idx]);
    float2 hl = __ldcs(&hl2[idx]);
    float2 hh = __ldcs(&hh2[idx]);

    float ax, bx, cx, dx, ay, by, cy, dy;
    {
        float s0, s1, d0, d1;
        s0 = ll.x + lh.x; s1 = hl.x + hh.x; d0 = ll.x - lh.x; d1 = hl.x - hh.x;
        ax = 0.5f * (s0 + s1); bx = 0.5f * (s0 - s1);
        cx = 0.5f * (d0 + d1); dx = 0.5f * (d0 - d1);
        s0 = ll.y + lh.y; s1 = hl.y + hh.y; d0 = ll.y - lh.y; d1 = hl.y - hh.y;
        ay = 0.5f * (s0 + s1); by = 0.5f * (s0 - s1);
        cy = 0.5f * (d0 + d1); dy = 0.5f * (d0 - d1);
    }

    // idx = plane*8192 + row*64 + col2 (col2 in [0,64), row in [0,128), plane in [0,1024)).
    unsigned col2  = idx & (W2F2 - 1);        // 0..63
    unsigned row   = (idx >> 6) & (H2 - 1);   // 0..127
    unsigned plane = idx >> 13;               // 0..1023

    // Output base (float4 units): plane*32768 + (2*row)*64 + col2. Max < 2^25.
    unsigned base = plane * (2u * H2 * OUT_ROW_F4)
                  + (2u * row) * OUT_ROW_F4
                  + col2;

    // Row 2i: [a0,b0,a1,b1]; Row 2i+1: [c0,d0,c1,d1] — one dense float4 each.
    __stcs(&out4[base],              make_float4(ax, bx, ay, by));
    __stcs(&out4[base + OUT_ROW_F4], make_float4(cx, dx, cy, dy));
}

extern "C" void kernel_launch(void* const* d_in, const int* in_sizes, int n_in,
                              void* d_out, int out_size)
{
    const float2* ll = (const float2*)d_in[0];
    const float2* lh = (const float2*)d_in[1];
    const float2* hl = (const float2*)d_in[2];
    const float2* hh = (const float2*)d_in[3];
    float4* out = (float4*)d_out;

    int n_groups = in_sizes[0] / 2;              // 2^23
    int grid = (n_groups + BLOCK - 1) / BLOCK;   // 16384
    idwt_haar_kernel<<<grid, BLOCK>>>(ll, lh, hl, hh, out);
}

// round 13
// speedup vs baseline: 1.0287x; 1.0115x over previous
#include <cuda_runtime.h>

// IDWT (inverse Haar) — FINAL: streaming kernel, dense-store layout + .cs hints.
// Confirmation re-bench of the R12 best-total configuration (unchanged).
// Inputs: LL, LH, HL, HH each [B=16, C=64, H2=128, W2=128] fp32.
// Output: [16, 64, 256, 256] fp32.
// out[2i,2j]=a, out[2i,2j+1]=b, out[2i+1,2j]=c, out[2i+1,2j+1]=d where
//   a=(LL+LH+HL+HH)/2, b=(LL+LH-HL-HH)/2, c=(LL-LH+HL-HH)/2, d=(LL-LH-HL+HH)/2
//
// One thread per float2 (2 coefficients). Each thread writes exactly one
// float4 into each of two output rows; consecutive lanes hit consecutive
// float4s -> every STG.128 is a dense 512B warp transaction. Touch-once
// traffic -> .cs streaming policy on all loads/stores. Measured at the
// mixed-R/W HBM ceiling (~6.45 TB/s, DRAM ~81%): loads/stores fully dense,
// regs=18, no further pipe has headroom to convert.

static constexpr int W2 = 128;                   // input width
static constexpr int H2 = 128;                   // input height
static constexpr int W2F2 = W2 / 2;              // float2 groups per input row = 64
static constexpr int OUT_ROW_F4 = (2 * W2) / 4;  // 64 float4 per output row

static constexpr int BLOCK = 512;

__global__ void __launch_bounds__(BLOCK) idwt_haar_kernel(
    const float2* __restrict__ ll2,
    const float2* __restrict__ lh2,
    const float2* __restrict__ hl2,
    const float2* __restrict__ hh2,
    float4* __restrict__ out4)
{
    unsigned idx = blockIdx.x * BLOCK + threadIdx.x;   // one per 2 input coeffs

    float2 ll = __ldcs(&ll2[idx]);
    float2 lh = __ldcs(&lh2[idx]);
    float2 hl = __ldcs(&hl2[idx]);
    float2 hh = __ldcs(&hh2[idx]);

    float ax, bx, cx, dx, ay, by, cy, dy;
    {
        float s0, s1, d0, d1;
        s0 = ll.x + lh.x; s1 = hl.x + hh.x; d0 = ll.x - lh.x; d1 = hl.x - hh.x;
        ax = 0.5f * (s0 + s1); bx = 0.5f * (s0 - s1);
        cx = 0.5f * (d0 + d1); dx = 0.5f * (d0 - d1);
        s0 = ll.y + lh.y; s1 = hl.y + hh.y; d0 = ll.y - lh.y; d1 = hl.y - hh.y;
        ay = 0.5f * (s0 + s1); by = 0.5f * (s0 - s1);
        cy = 0.5f * (d0 + d1); dy = 0.5f * (d0 - d1);
    }

    // idx = plane*8192 + row*64 + col2 (col2 in [0,64), row in [0,128), plane in [0,1024)).
    unsigned col2  = idx & (W2F2 - 1);        // 0..63
    unsigned row   = (idx >> 6) & (H2 - 1);   // 0..127
    unsigned plane = idx >> 13;               // 0..1023

    // Output base (float4 units): plane*32768 + (2*row)*64 + col2. Max < 2^25.
    unsigned base = plane * (2u * H2 * OUT_ROW_F4)
                  + (2u * row) * OUT_ROW_F4
                  + col2;

    // Row 2i: [a0,b0,a1,b1]; Row 2i+1: [c0,d0,c1,d1] — one dense float4 each.
    __stcs(&out4[base],              make_float4(ax, bx, ay, by));
    __stcs(&out4[base + OUT_ROW_F4], make_float4(cx, dx, cy, dy));
}

extern "C" void kernel_launch(void* const* d_in, const int* in_sizes, int n_in,
                              void* d_out, int out_size)
{
    const float2* ll = (const float2*)d_in[0];
    const float2* lh = (const float2*)d_in[1];
    const float2* hl = (const float2*)d_in[2];
    const float2* hh = (const float2*)d_in[3];
    float4* out = (float4*)d_out;

    int n_groups = in_sizes[0] / 2;              // 2^23
    int grid = (n_groups + BLOCK - 1) / BLOCK;   // 16384
    idwt_haar_kernel<<<grid, BLOCK>>>(ll, lh, hl, hh, out);
}